// round 7
// baseline (speedup 1.0000x reference)
#include <cuda_runtime.h>
#include <cuda_bf16.h>
#include <cstdint>

#define NN 4096
#define BB 512
#define DTc 0.1f

// ---- row partition between tensor and fp32 paths ----
#define TTILES 23                 // tensor m-tiles (128 rows each): rows 0..2943
#define FTILES 9                  // fp32 m-tiles: rows 2944..4095
#define FOFF (TTILES * 128)       // 2944

// GEMM tiling (mma.sync bf16)
#define BM 128
#define BN 128
#define BKt 32
#define NKT (NN / BKt)
#define ROWB 80
#define TILEB (128 * ROWB)
#define STAGEB (4 * TILEB)
#define NSTG 3
#define SMEM_BYTES (NSTG * STAGEB)   // 122880

// fp32 SGEMM tiling (R1-proven)
#define FBM 128
#define FBN 64
#define FBK 16

// --------------------------------------------------------------------------
__device__ __align__(256) __nv_bfloat16 g_Ahi[(size_t)NN * NN];    // 32 MB
__device__ __align__(256) __nv_bfloat16 g_Alo[(size_t)NN * NN];    // 32 MB
__device__ __align__(256) float g_P22[(size_t)NN * NN];            // 64 MB (fp32 path)
__device__ __align__(256) __nv_bfloat16 g_Bhi[2][(size_t)BB * NN]; // 2x4 MB
__device__ __align__(256) __nv_bfloat16 g_Blo[2][(size_t)BB * NN]; // 2x4 MB
__device__ float g_x[2][2 * BB];
__device__ float g_zha[2][BB];

// --------------------------------------------------------------------------
__device__ __forceinline__ uint32_t smem_u32(const void* p) {
    return (uint32_t)__cvta_generic_to_shared((void*)p);
}
__device__ __forceinline__ void cp16(uint32_t dst, const void* src) {
    asm volatile("cp.async.cg.shared.global [%0], [%1], 16;" :: "r"(dst), "l"(src) : "memory");
}
__device__ __forceinline__ void ldsm4(uint32_t* r, uint32_t a) {
    asm volatile("ldmatrix.sync.aligned.m8n8.x4.shared.b16 {%0,%1,%2,%3}, [%4];"
                 : "=r"(r[0]), "=r"(r[1]), "=r"(r[2]), "=r"(r[3]) : "r"(a));
}
__device__ __forceinline__ void ldsm2(uint32_t* r, uint32_t a) {
    asm volatile("ldmatrix.sync.aligned.m8n8.x2.shared.b16 {%0,%1}, [%2];"
                 : "=r"(r[0]), "=r"(r[1]) : "r"(a));
}
__device__ __forceinline__ void mma_bf16(float* d, const uint32_t* a, const uint32_t* b) {
    asm("mma.sync.aligned.m16n8k16.row.col.f32.bf16.bf16.f32 "
        "{%0,%1,%2,%3}, {%4,%5,%6,%7}, {%8,%9}, {%0,%1,%2,%3};"
        : "+f"(d[0]), "+f"(d[1]), "+f"(d[2]), "+f"(d[3])
        : "r"(a[0]), "r"(a[1]), "r"(a[2]), "r"(a[3]), "r"(b[0]), "r"(b[1]));
}

// --------------------------------------------------------------------------
// Build P22 (fp32) and its bf16 hi/lo split; zero zh accumulators.
// --------------------------------------------------------------------------
__global__ void build_split_kernel(const float* __restrict__ W,
                                   const float* __restrict__ U,
                                   const float* __restrict__ V,
                                   const float* __restrict__ Mv,
                                   const float* __restrict__ Z,
                                   const float* __restrict__ Cc,
                                   const float* __restrict__ Bm) {
    if (blockIdx.x == 0 && blockIdx.y == 0) {
        int tIdx = threadIdx.x;
        g_zha[0][tIdx] = 0.f;       g_zha[1][tIdx] = 0.f;
        g_zha[0][tIdx + 256] = 0.f; g_zha[1][tIdx + 256] = 0.f;
    }
    int i = blockIdx.y;
    int j = (blockIdx.x * blockDim.x + threadIdx.x) * 4;
    float cb = Cc[0] * Bm[0] + Cc[1] * Bm[1];
    float mi = Mv[i];
    float u0 = U[i * 4 + 0], u1 = U[i * 4 + 1], u2 = U[i * 4 + 2], u3 = U[i * 4 + 3];
    float4 w = *(const float4*)(W + (size_t)i * NN + j);
    const float* wp = &w.x;
    union { __nv_bfloat16 h[4]; uint2 u; } ph, pl;
    float4 fo;
    float* fop = &fo.x;
#pragma unroll
    for (int jj = 0; jj < 4; ++jj) {
        int jc = j + jj;
        float4 vv = *(const float4*)(V + (size_t)jc * 4);
        float uv = u0 * vv.x + u1 * vv.y + u2 * vv.z + u3 * vv.w;
        float val = DTc * (wp[jj] + uv) + cb * mi * Z[jc];
        if (jc == i) val += 1.0f - DTc;
        fop[jj] = val;
        __nv_bfloat16 hi = __float2bfloat16(val);
        ph.h[jj] = hi;
        pl.h[jj] = __float2bfloat16(val - __bfloat162float(hi));
    }
    *(float4*)(g_P22 + (size_t)i * NN + j) = fo;
    *(uint2*)(g_Ahi + (size_t)i * NN + j) = ph.u;
    *(uint2*)(g_Alo + (size_t)i * NN + j) = pl.u;
}

// --------------------------------------------------------------------------
// init_all: h0 -> traj_0 h-block + transposed bf16 split + zh0 + x init
// --------------------------------------------------------------------------
__global__ void init_all_kernel(const float* __restrict__ h0,
                                const float* __restrict__ x0,
                                const float* __restrict__ x1,
                                const float* __restrict__ Z,
                                float* __restrict__ traj0h) {
    __shared__ float t[32][33];
    __shared__ float zs[8][33];
    int m0 = blockIdx.x * 32, b0 = blockIdx.y * 32;
    int tx = threadIdx.x, ty = threadIdx.y;
    if (blockIdx.x == 0 && blockIdx.y == 0) {
        int tid = ty * 32 + tx;
#pragma unroll
        for (int it = 0; it < 2; ++it) {
            int b = tid + it * 256;
            g_x[0][b] = x0[b];
            g_x[0][BB + b] = x1[b];
        }
    }
#pragma unroll
    for (int j = 0; j < 32; j += 8) {
        size_t a = (size_t)(m0 + ty + j) * BB + b0 + tx;
        float v = h0[a];
        traj0h[a] = v;
        t[ty + j][tx] = v;
    }
    __syncthreads();
    {
        float s = 0.f;
#pragma unroll
        for (int i = 0; i < 4; ++i) {
            int r = ty * 4 + i;
            s = fmaf(Z[m0 + r], t[r][tx], s);
        }
        zs[ty][tx] = s;
    }
#pragma unroll
    for (int j = 0; j < 32; j += 8) {
        float v = t[tx][ty + j];
        size_t o = (size_t)(b0 + ty + j) * NN + m0 + tx;
        __nv_bfloat16 hi = __float2bfloat16(v);
        g_Bhi[0][o] = hi;
        g_Blo[0][o] = __float2bfloat16(v - __bfloat162float(hi));
    }
    __syncthreads();
    if (ty == 0) {
        float s = 0.f;
#pragma unroll
        for (int r = 0; r < 8; ++r) s += zs[r][tx];
        atomicAdd(&g_zha[0][b0 + tx], s);
    }
}

// --------------------------------------------------------------------------
// Tensor-path step kernel (rows 0..FOFF-1). grid (4, TTILES), block 256.
// Also: block (0,0) does the fused x-update for step t.
// --------------------------------------------------------------------------
__device__ __forceinline__ void load_stage(uint32_t stg, int kt, int tid,
                                           int rowBase, int colBase,
                                           const __nv_bfloat16* Ah, const __nv_bfloat16* Al,
                                           const __nv_bfloat16* Bh, const __nv_bfloat16* Bl) {
#pragma unroll
    for (int i = 0; i < 8; ++i) {
        int ch = i * 256 + tid;
        int tile = ch >> 9;
        int r = (ch >> 2) & 127;
        int c = ch & 3;
        const __nv_bfloat16* base = (tile == 0) ? Ah : (tile == 1) ? Al : (tile == 2) ? Bh : Bl;
        int rb = (tile < 2) ? rowBase : colBase;
        const char* src = (const char*)base + ((size_t)(rb + r) * NN + kt * BKt + c * 8) * 2;
        uint32_t dst = stg + tile * TILEB + r * ROWB + c * 16;
        cp16(dst, src);
    }
}

__global__ void __launch_bounds__(256, 1) gemm_tensor_kernel(
    int p, int do_mma,
    const float* __restrict__ Mv,
    const float* __restrict__ Cc, const float* __restrict__ Amat,
    const float* __restrict__ Bm, const float* __restrict__ Z,
    float* __restrict__ trajh_next,
    float* __restrict__ trajx_cur,
    float* __restrict__ con_cur) {
    extern __shared__ __align__(128) char smem[];
    uint32_t sb = smem_u32(smem);
    int tid = threadIdx.x;
    int lane = tid & 31;
    int wid = tid >> 5;
    int rowBase = blockIdx.y * BM;
    int colBase = blockIdx.x * BN;
    int q2 = p ^ 1;

    if (blockIdx.x == 0 && blockIdx.y == 0) {
#pragma unroll
        for (int it = 0; it < 2; ++it) {
            int b = tid + it * 256;
            float zh = g_zha[p][b];
            g_zha[p][b] = 0.f;
            float xv0 = g_x[p][b], xv1 = g_x[p][BB + b];
            con_cur[b] = Bm[1] * zh;
            trajx_cur[b] = xv0;
            trajx_cur[BB + b] = xv1;
            g_x[q2][b] = Amat[0] * xv0 + Amat[1] * xv1 + Bm[0] * zh;
            g_x[q2][BB + b] = Amat[2] * xv0 + Amat[3] * xv1 + Bm[1] * zh;
        }
    }
    if (!do_mma) return;

    const __nv_bfloat16* Ah = g_Ahi;
    const __nv_bfloat16* Al = g_Alo;
    const __nv_bfloat16* Bh = g_Bhi[p];
    const __nv_bfloat16* Bl = g_Blo[p];

    int mb = (wid >> 2) * 64;
    int nb = (wid & 3) * 32;
    uint32_t aRow = (uint32_t)(mb + (lane & 15));
    uint32_t aK = (uint32_t)((lane >> 4) * 8);
    uint32_t bRow = (uint32_t)(nb + (lane & 7));
    uint32_t bK = (uint32_t)(((lane >> 3) & 1) * 8);

    float acc[4][4][4];
#pragma unroll
    for (int mi = 0; mi < 4; ++mi)
#pragma unroll
        for (int ni = 0; ni < 4; ++ni)
#pragma unroll
            for (int k = 0; k < 4; ++k) acc[mi][ni][k] = 0.f;

#pragma unroll
    for (int s = 0; s < NSTG; ++s) {
        load_stage(sb + s * STAGEB, s, tid, rowBase, colBase, Ah, Al, Bh, Bl);
        asm volatile("cp.async.commit_group;" ::: "memory");
    }

    for (int kt = 0; kt < NKT; ++kt) {
        asm volatile("cp.async.wait_group 2;" ::: "memory");
        __syncthreads();
        uint32_t stg = sb + (uint32_t)(kt % NSTG) * STAGEB;
#pragma unroll
        for (int ks = 0; ks < BKt; ks += 16) {
            uint32_t ah[4][4], al2[4][4], bh2[4][2], bl2[4][2];
#pragma unroll
            for (int mi = 0; mi < 4; ++mi) {
                uint32_t a = stg + (aRow + mi * 16) * ROWB + (aK + ks) * 2;
                ldsm4(ah[mi], a);
                ldsm4(al2[mi], a + TILEB);
            }
#pragma unroll
            for (int ni = 0; ni < 4; ++ni) {
                uint32_t a = stg + 2 * TILEB + (bRow + ni * 8) * ROWB + (bK + ks) * 2;
                ldsm2(bh2[ni], a);
                ldsm2(bl2[ni], a + TILEB);
            }
#pragma unroll
            for (int mi = 0; mi < 4; ++mi)
#pragma unroll
                for (int ni = 0; ni < 4; ++ni) {
                    mma_bf16(acc[mi][ni], ah[mi], bh2[ni]);
                    mma_bf16(acc[mi][ni], ah[mi], bl2[ni]);
                    mma_bf16(acc[mi][ni], al2[mi], bh2[ni]);
                }
        }
        __syncthreads();
        if (kt + NSTG < NKT)
            load_stage(stg, kt + NSTG, tid, rowBase, colBase, Ah, Al, Bh, Bl);
        asm volatile("cp.async.commit_group;" ::: "memory");
    }
    __syncthreads();

    // ---- Epilogue pass 1: frags -> smem Cst [n][132] ----
    float* Cst = (float*)smem;
#pragma unroll
    for (int mi = 0; mi < 4; ++mi)
#pragma unroll
        for (int ni = 0; ni < 4; ++ni) {
            int m = mb + mi * 16 + (lane >> 2);
            int n = nb + ni * 8 + (lane & 3) * 2;
            Cst[n * 132 + m] = acc[mi][ni][0];
            Cst[(n + 1) * 132 + m] = acc[mi][ni][1];
            Cst[n * 132 + m + 8] = acc[mi][ni][2];
            Cst[(n + 1) * 132 + m + 8] = acc[mi][ni][3];
        }
    __syncthreads();

    float CA0 = Cc[0] * Amat[0] + Cc[1] * Amat[2];
    float CA1 = Cc[0] * Amat[1] + Cc[1] * Amat[3];
    {
        int n = tid >> 1;
        int m0 = (tid & 1) * 64;
        float e = CA0 * g_x[p][colBase + n] + CA1 * g_x[p][BB + colBase + n];
        __nv_bfloat16* __restrict__ Bhn = g_Bhi[q2];
        __nv_bfloat16* __restrict__ Bln = g_Blo[q2];
        size_t obase = (size_t)(colBase + n) * NN + rowBase;
        float zp = 0.f;
#pragma unroll
        for (int q = 0; q < 16; ++q) {
            int m = m0 + q * 4;
            float4 c = *(float4*)&Cst[n * 132 + m];
            float4 mv4 = *(const float4*)&Mv[rowBase + m];
            float4 z4 = *(const float4*)&Z[rowBase + m];
            float4 v;
            v.x = c.x + DTc * mv4.x * e;
            v.y = c.y + DTc * mv4.y * e;
            v.z = c.z + DTc * mv4.z * e;
            v.w = c.w + DTc * mv4.w * e;
            *(float4*)&Cst[n * 132 + m] = v;
            zp += z4.x * v.x + z4.y * v.y + z4.z * v.z + z4.w * v.w;
            union { __nv_bfloat16 h[4]; uint2 u; } ph, pl;
            const float* vp = &v.x;
#pragma unroll
            for (int j = 0; j < 4; ++j) {
                __nv_bfloat16 hi = __float2bfloat16(vp[j]);
                ph.h[j] = hi;
                pl.h[j] = __float2bfloat16(vp[j] - __bfloat162float(hi));
            }
            *(uint2*)&Bhn[obase + m] = ph.u;
            *(uint2*)&Bln[obase + m] = pl.u;
        }
        zp += __shfl_xor_sync(0xFFFFFFFFu, zp, 1);
        if ((tid & 1) == 0)
            atomicAdd(&g_zha[q2][colBase + n], zp);
    }
    __syncthreads();

    {
        int m = tid >> 1;
        int n0 = (tid & 1) * 64;
        size_t tb = (size_t)(rowBase + m) * BB + colBase + n0;
#pragma unroll
        for (int q = 0; q < 16; ++q) {
            float4 v;
            v.x = Cst[(n0 + q * 4 + 0) * 132 + m];
            v.y = Cst[(n0 + q * 4 + 1) * 132 + m];
            v.z = Cst[(n0 + q * 4 + 2) * 132 + m];
            v.w = Cst[(n0 + q * 4 + 3) * 132 + m];
            *(float4*)&trajh_next[tb + q * 4] = v;
        }
    }
}

// --------------------------------------------------------------------------
// fp32-path step kernel (rows FOFF..NN-1). grid (8, FTILES), block 256.
// B operand = current h (fp32) read straight from traj_t's h-block.
// Fused epilogue: trajh_next, Bhi/Blo split, zh partials, P21 term.
// --------------------------------------------------------------------------
__global__ __launch_bounds__(256) void gemm_fp32_kernel(
    int p,
    const float* __restrict__ hcur,      // traj_t h-block [NN][BB]
    const float* __restrict__ Mv,
    const float* __restrict__ Cc, const float* __restrict__ Amat,
    const float* __restrict__ Z,
    float* __restrict__ trajh_next) {
    __shared__ float As[2][FBK][FBM];
    __shared__ float Bs[2][FBK][FBN];

    int tid = threadIdx.x;
    int ty = tid >> 4;
    int tx = tid & 15;
    int rowBase = FOFF + blockIdx.y * FBM;
    int colBase = blockIdx.x * FBN;
    int q2 = p ^ 1;

    const float* Ag = g_P22;
    int ar0 = tid >> 2;
    int ac = (tid & 3) * 4;
    int br = tid >> 4;
    int bc = (tid & 15) * 4;

    const float* Aptr = Ag + (size_t)rowBase * NN;
    const float* Bptr = hcur + colBase;

    float4 pa0 = *(const float4*)(Aptr + (size_t)ar0 * NN + ac);
    float4 pa1 = *(const float4*)(Aptr + (size_t)(ar0 + 64) * NN + ac);
    float4 pb  = *(const float4*)(Bptr + (size_t)br * BB + bc);

    As[0][ac + 0][ar0] = pa0.x; As[0][ac + 1][ar0] = pa0.y;
    As[0][ac + 2][ar0] = pa0.z; As[0][ac + 3][ar0] = pa0.w;
    As[0][ac + 0][ar0 + 64] = pa1.x; As[0][ac + 1][ar0 + 64] = pa1.y;
    As[0][ac + 2][ar0 + 64] = pa1.z; As[0][ac + 3][ar0 + 64] = pa1.w;
    *(float4*)&Bs[0][br][bc] = pb;
    __syncthreads();

    float acc[8][4];
#pragma unroll
    for (int i = 0; i < 8; ++i)
#pragma unroll
        for (int j = 0; j < 4; ++j) acc[i][j] = 0.f;

    int buf = 0;
    for (int k0 = 0; k0 < NN; k0 += FBK) {
        int nk = k0 + FBK;
        if (nk < NN) {
            pa0 = *(const float4*)(Aptr + (size_t)ar0 * NN + nk + ac);
            pa1 = *(const float4*)(Aptr + (size_t)(ar0 + 64) * NN + nk + ac);
            pb  = *(const float4*)(Bptr + (size_t)(nk + br) * BB + bc);
        }
#pragma unroll
        for (int k = 0; k < FBK; ++k) {
            float4 a0 = *(float4*)&As[buf][k][ty * 8];
            float4 a1 = *(float4*)&As[buf][k][ty * 8 + 4];
            float4 b0 = *(float4*)&Bs[buf][k][tx * 4];
            const float ra[8] = {a0.x, a0.y, a0.z, a0.w, a1.x, a1.y, a1.z, a1.w};
            const float rb[4] = {b0.x, b0.y, b0.z, b0.w};
#pragma unroll
            for (int i = 0; i < 8; ++i)
#pragma unroll
                for (int j = 0; j < 4; ++j)
                    acc[i][j] = fmaf(ra[i], rb[j], acc[i][j]);
        }
        if (nk < NN) {
            int nb = buf ^ 1;
            As[nb][ac + 0][ar0] = pa0.x; As[nb][ac + 1][ar0] = pa0.y;
            As[nb][ac + 2][ar0] = pa0.z; As[nb][ac + 3][ar0] = pa0.w;
            As[nb][ac + 0][ar0 + 64] = pa1.x; As[nb][ac + 1][ar0 + 64] = pa1.y;
            As[nb][ac + 2][ar0 + 64] = pa1.z; As[nb][ac + 3][ar0 + 64] = pa1.w;
            *(float4*)&Bs[nb][br][bc] = pb;
            __syncthreads();
            buf = nb;
        }
    }

    // ---- Fused epilogue ----
    float CA0 = Cc[0] * Amat[0] + Cc[1] * Amat[2];
    float CA1 = Cc[0] * Amat[1] + Cc[1] * Amat[3];
    int myRow = rowBase + ty * 8;
    float e[4], zp[4];
#pragma unroll
    for (int j = 0; j < 4; ++j) {
        int col = colBase + tx * 4 + j;
        e[j] = CA0 * g_x[p][col] + CA1 * g_x[p][BB + col];
        zp[j] = 0.f;
    }
    __nv_bfloat16 hiA[4][8], loA[4][8];
#pragma unroll
    for (int i = 0; i < 8; ++i) {
        int m = myRow + i;
        float msc = DTc * Mv[m];
        float zm = Z[m];
        float4 v;
        v.x = acc[i][0] + msc * e[0];
        v.y = acc[i][1] + msc * e[1];
        v.z = acc[i][2] + msc * e[2];
        v.w = acc[i][3] + msc * e[3];
        *(float4*)&trajh_next[(size_t)m * BB + colBase + tx * 4] = v;
        const float* vp = &v.x;
#pragma unroll
        for (int j = 0; j < 4; ++j) {
            zp[j] = fmaf(zm, vp[j], zp[j]);
            __nv_bfloat16 hi = __float2bfloat16(vp[j]);
            hiA[j][i] = hi;
            loA[j][i] = __float2bfloat16(vp[j] - __bfloat162float(hi));
        }
    }
    __nv_bfloat16* __restrict__ Bhn = g_Bhi[q2];
    __nv_bfloat16* __restrict__ Bln = g_Blo[q2];
#pragma unroll
    for (int j = 0; j < 4; ++j) {
        int col = colBase + tx * 4 + j;
        size_t o = (size_t)col * NN + myRow;
        *(uint4*)&Bhn[o] = *(uint4*)&hiA[j][0];
        *(uint4*)&Bln[o] = *(uint4*)&loA[j][0];
        atomicAdd(&g_zha[q2][col], zp[j]);
    }
}

// --------------------------------------------------------------------------
extern "C" void kernel_launch(void* const* d_in, const int* in_sizes, int n_in,
                              void* d_out, int out_size) {
    const float* x0 = (const float*)d_in[0];
    const float* x1 = (const float*)d_in[1];
    const float* h0 = (const float*)d_in[2];
    const float* A  = (const float*)d_in[3];
    const float* Bm = (const float*)d_in[4];
    const float* C  = (const float*)d_in[5];
    const float* Mv = (const float*)d_in[6];
    const float* Z  = (const float*)d_in[7];
    const float* U  = (const float*)d_in[8];
    const float* V  = (const float*)d_in[9];
    const float* W  = (const float*)d_in[10];

    long long per_step_full = (long long)BB * (NN + 2 + 1);
    int steps = (int)((long long)out_size / per_step_full);
    if ((long long)steps * per_step_full != (long long)out_size)
        steps = (int)((long long)out_size / ((long long)BB * (NN + 2)));

    float* out  = (float*)d_out;
    float* traj = out;
    float* con  = out + (size_t)steps * (NN + 2) * BB;

    cudaFuncSetAttribute(gemm_tensor_kernel,
                         cudaFuncAttributeMaxDynamicSharedMemorySize, SMEM_BYTES);

    cudaStream_t s2;
    cudaEvent_t evA, evB;
    cudaStreamCreateWithFlags(&s2, cudaStreamNonBlocking);
    cudaEventCreateWithFlags(&evA, cudaEventDisableTiming);
    cudaEventCreateWithFlags(&evB, cudaEventDisableTiming);

    build_split_kernel<<<dim3(NN / 4 / 256, NN), 256>>>(W, U, V, Mv, Z, C, Bm);
    init_all_kernel<<<dim3(NN / 32, BB / 32), dim3(32, 8)>>>(h0, x0, x1, Z, traj + 2 * BB);

    for (int t = 0; t < steps; ++t) {
        int p = t & 1;
        int do_mma = (t < steps - 1);
        float* traj_t = traj + (size_t)t * (NN + 2) * BB;
        float* trajh_next = traj + (size_t)(t + 1) * (NN + 2) * BB + 2 * BB;
        if (!do_mma) trajh_next = traj_t + 2 * BB;   // unused, keep in-bounds

        if (do_mma) {
            // fork: fp32 kernel on s2, tensor kernel on default stream
            cudaEventRecord(evA, 0);
            cudaStreamWaitEvent(s2, evA, 0);
            gemm_fp32_kernel<<<dim3(BB / FBN, FTILES), 256, 0, s2>>>(
                p, traj_t + 2 * BB, Mv, C, A, Z, trajh_next);
            gemm_tensor_kernel<<<dim3(BB / BN, TTILES), 256, SMEM_BYTES>>>(
                p, 1, Mv, C, A, Bm, Z, trajh_next, traj_t, con + (size_t)t * BB);
            cudaEventRecord(evB, s2);
            cudaStreamWaitEvent(0, evB, 0);
        } else {
            gemm_tensor_kernel<<<dim3(BB / BN, TTILES), 256, SMEM_BYTES>>>(
                p, 0, Mv, C, A, Bm, Z, trajh_next, traj_t, con + (size_t)t * BB);
        }
    }

    cudaEventDestroy(evA);
    cudaEventDestroy(evB);
    cudaStreamDestroy(s2);
}

// round 8
// speedup vs baseline: 2.1626x; 2.1626x over previous
#include <cuda_runtime.h>
#include <cuda_bf16.h>
#include <cstdint>

#define NN 4096
#define BB 512
#define DTc 0.1f

// GEMM tiling (mma.sync bf16)
#define BM 128
#define BN 128
#define BKt 32
#define NCHUNK 128                   // K-chunks per tile (4096/32)
#define NTILES 128                   // 32 M x 4 N
#define TOTC (NTILES * NCHUNK)       // 16384
#define ROWB 80
#define TILEB (128 * ROWB)
#define STAGEB (4 * TILEB)
#define NSTG 3
#define SMEM_BYTES (NSTG * STAGEB)   // 122880

// --------------------------------------------------------------------------
__device__ __align__(256) __nv_bfloat16 g_Ahi[(size_t)NN * NN];    // 32 MB
__device__ __align__(256) __nv_bfloat16 g_Alo[(size_t)NN * NN];    // 32 MB
__device__ __align__(256) __nv_bfloat16 g_Bhi[2][(size_t)BB * NN]; // 2x4 MB
__device__ __align__(256) __nv_bfloat16 g_Blo[2][(size_t)BB * NN]; // 2x4 MB
__device__ __align__(256) float g_Cpart[(size_t)NTILES * 3 * 128 * 128]; // 25.2 MB
__device__ int g_cnt[NTILES];        // zero-init; kernel restores zeros
__device__ float g_x[2][2 * BB];
__device__ float g_zha[2][BB];

// --------------------------------------------------------------------------
__device__ __forceinline__ uint32_t smem_u32(const void* p) {
    return (uint32_t)__cvta_generic_to_shared((void*)p);
}
__device__ __forceinline__ void cp16(uint32_t dst, const void* src) {
    asm volatile("cp.async.cg.shared.global [%0], [%1], 16;" :: "r"(dst), "l"(src) : "memory");
}
__device__ __forceinline__ void ldsm4(uint32_t* r, uint32_t a) {
    asm volatile("ldmatrix.sync.aligned.m8n8.x4.shared.b16 {%0,%1,%2,%3}, [%4];"
                 : "=r"(r[0]), "=r"(r[1]), "=r"(r[2]), "=r"(r[3]) : "r"(a));
}
__device__ __forceinline__ void ldsm2(uint32_t* r, uint32_t a) {
    asm volatile("ldmatrix.sync.aligned.m8n8.x2.shared.b16 {%0,%1}, [%2];"
                 : "=r"(r[0]), "=r"(r[1]) : "r"(a));
}
__device__ __forceinline__ void mma_bf16(float* d, const uint32_t* a, const uint32_t* b) {
    asm("mma.sync.aligned.m16n8k16.row.col.f32.bf16.bf16.f32 "
        "{%0,%1,%2,%3}, {%4,%5,%6,%7}, {%8,%9}, {%0,%1,%2,%3};"
        : "+f"(d[0]), "+f"(d[1]), "+f"(d[2]), "+f"(d[3])
        : "r"(a[0]), "r"(a[1]), "r"(a[2]), "r"(a[3]), "r"(b[0]), "r"(b[1]));
}

// --------------------------------------------------------------------------
// Build A_hi/A_lo (bf16 split of P22); zero zh accumulators.
// --------------------------------------------------------------------------
__global__ void build_split_kernel(const float* __restrict__ W,
                                   const float* __restrict__ U,
                                   const float* __restrict__ V,
                                   const float* __restrict__ Mv,
                                   const float* __restrict__ Z,
                                   const float* __restrict__ Cc,
                                   const float* __restrict__ Bm) {
    if (blockIdx.x == 0 && blockIdx.y == 0) {
        int tIdx = threadIdx.x;
        g_zha[0][tIdx] = 0.f;       g_zha[1][tIdx] = 0.f;
        g_zha[0][tIdx + 256] = 0.f; g_zha[1][tIdx + 256] = 0.f;
        if (tIdx < NTILES) g_cnt[tIdx] = 0;
    }
    int i = blockIdx.y;
    int j = (blockIdx.x * blockDim.x + threadIdx.x) * 4;
    float cb = Cc[0] * Bm[0] + Cc[1] * Bm[1];
    float mi = Mv[i];
    float u0 = U[i * 4 + 0], u1 = U[i * 4 + 1], u2 = U[i * 4 + 2], u3 = U[i * 4 + 3];
    float4 w = *(const float4*)(W + (size_t)i * NN + j);
    const float* wp = &w.x;
    union { __nv_bfloat16 h[4]; uint2 u; } ph, pl;
#pragma unroll
    for (int jj = 0; jj < 4; ++jj) {
        int jc = j + jj;
        float4 vv = *(const float4*)(V + (size_t)jc * 4);
        float uv = u0 * vv.x + u1 * vv.y + u2 * vv.z + u3 * vv.w;
        float val = DTc * (wp[jj] + uv) + cb * mi * Z[jc];
        if (jc == i) val += 1.0f - DTc;
        __nv_bfloat16 hi = __float2bfloat16(val);
        ph.h[jj] = hi;
        pl.h[jj] = __float2bfloat16(val - __bfloat162float(hi));
    }
    *(uint2*)(g_Ahi + (size_t)i * NN + j) = ph.u;
    *(uint2*)(g_Alo + (size_t)i * NN + j) = pl.u;
}

// --------------------------------------------------------------------------
// init_all: h0 -> traj_0 h-block + transposed bf16 split + zh0 + x init
// --------------------------------------------------------------------------
__global__ void init_all_kernel(const float* __restrict__ h0,
                                const float* __restrict__ x0,
                                const float* __restrict__ x1,
                                const float* __restrict__ Z,
                                float* __restrict__ traj0h) {
    __shared__ float t[32][33];
    __shared__ float zs[8][33];
    int m0 = blockIdx.x * 32, b0 = blockIdx.y * 32;
    int tx = threadIdx.x, ty = threadIdx.y;
    if (blockIdx.x == 0 && blockIdx.y == 0) {
        int tid = ty * 32 + tx;
#pragma unroll
        for (int it = 0; it < 2; ++it) {
            int b = tid + it * 256;
            g_x[0][b] = x0[b];
            g_x[0][BB + b] = x1[b];
        }
    }
#pragma unroll
    for (int j = 0; j < 32; j += 8) {
        size_t a = (size_t)(m0 + ty + j) * BB + b0 + tx;
        float v = h0[a];
        traj0h[a] = v;
        t[ty + j][tx] = v;
    }
    __syncthreads();
    {
        float s = 0.f;
#pragma unroll
        for (int i = 0; i < 4; ++i) {
            int r = ty * 4 + i;
            s = fmaf(Z[m0 + r], t[r][tx], s);
        }
        zs[ty][tx] = s;
    }
#pragma unroll
    for (int j = 0; j < 32; j += 8) {
        float v = t[tx][ty + j];
        size_t o = (size_t)(b0 + ty + j) * NN + m0 + tx;
        __nv_bfloat16 hi = __float2bfloat16(v);
        g_Bhi[0][o] = hi;
        g_Blo[0][o] = __float2bfloat16(v - __bfloat162float(hi));
    }
    __syncthreads();
    if (ty == 0) {
        float s = 0.f;
#pragma unroll
        for (int r = 0; r < 8; ++r) s += zs[r][tx];
        atomicAdd(&g_zha[0][b0 + tx], s);
    }
}

// --------------------------------------------------------------------------
__device__ __forceinline__ void load_stage(uint32_t stg, int kt, int tid,
                                           int rowBase, int colBase,
                                           const __nv_bfloat16* Ah, const __nv_bfloat16* Al,
                                           const __nv_bfloat16* Bh, const __nv_bfloat16* Bl) {
#pragma unroll
    for (int i = 0; i < 8; ++i) {
        int ch = i * 256 + tid;
        int tile = ch >> 9;
        int r = (ch >> 2) & 127;
        int c = ch & 3;
        const __nv_bfloat16* base = (tile == 0) ? Ah : (tile == 1) ? Al : (tile == 2) ? Bh : Bl;
        int rb = (tile < 2) ? rowBase : colBase;
        const char* src = (const char*)base + ((size_t)(rb + r) * NN + kt * BKt + c * 8) * 2;
        uint32_t dst = stg + tile * TILEB + r * ROWB + c * 16;
        cp16(dst, src);
    }
}

// --------------------------------------------------------------------------
// Stream-K fused step kernel. grid = nsm CTAs, block 256.
//   Chunk space: tile = c>>7 (32M x 4N tiles), k-chunk = c&127 (K=32 each).
//   CTA cid owns chunks [cid*TOTC/nsm, (cid+1)*TOTC/nsm).
//   Per tile-segment: partial GEMM -> plain STG to g_Cpart slot -> fence ->
//   counter add; last finisher sums slots + runs the fused epilogue.
// --------------------------------------------------------------------------
__global__ void __launch_bounds__(256, 1) gemm_streamk_kernel(
    int p, int do_mma, int nsm,
    const float* __restrict__ Mv,
    const float* __restrict__ Cc, const float* __restrict__ Amat,
    const float* __restrict__ Bm, const float* __restrict__ Z,
    float* __restrict__ trajh_next,
    float* __restrict__ trajx_cur,
    float* __restrict__ con_cur) {
    extern __shared__ __align__(128) char smem[];
    __shared__ int sflag;
    uint32_t sb = smem_u32(smem);
    int tid = threadIdx.x;
    int lane = tid & 31;
    int wid = tid >> 5;
    int q2 = p ^ 1;

    // ---- fused x-update (step t), CTA 0 only ----
    if (blockIdx.x == 0) {
#pragma unroll
        for (int it = 0; it < 2; ++it) {
            int b = tid + it * 256;
            float zh = g_zha[p][b];
            g_zha[p][b] = 0.f;
            float xv0 = g_x[p][b], xv1 = g_x[p][BB + b];
            con_cur[b] = Bm[1] * zh;
            trajx_cur[b] = xv0;
            trajx_cur[BB + b] = xv1;
            g_x[q2][b] = Amat[0] * xv0 + Amat[1] * xv1 + Bm[0] * zh;
            g_x[q2][BB + b] = Amat[2] * xv0 + Amat[3] * xv1 + Bm[1] * zh;
        }
    }
    if (!do_mma) return;

    const __nv_bfloat16* Ah = g_Ahi;
    const __nv_bfloat16* Al = g_Alo;
    const __nv_bfloat16* Bh = g_Bhi[p];
    const __nv_bfloat16* Bl = g_Blo[p];

    int cid = blockIdx.x;
    int c0 = (int)(((long long)cid * TOTC) / nsm);
    int c1 = (int)(((long long)(cid + 1) * TOTC) / nsm);

    int mb = (wid >> 2) * 64;
    int nb = (wid & 3) * 32;
    uint32_t aRow = (uint32_t)(mb + (lane & 15));
    uint32_t aK = (uint32_t)((lane >> 4) * 8);
    uint32_t bRow = (uint32_t)(nb + (lane & 7));
    uint32_t bK = (uint32_t)(((lane >> 3) & 1) * 8);

    while (c0 < c1) {
        int tile = c0 >> 7;
        int kt0 = c0 & 127;
        int kcnt = min(NCHUNK - kt0, c1 - c0);
        int rowBase = (tile >> 2) * BM;
        int colBase = (tile & 3) * BN;

        float acc[4][4][4];
#pragma unroll
        for (int mi = 0; mi < 4; ++mi)
#pragma unroll
            for (int ni = 0; ni < 4; ++ni)
#pragma unroll
                for (int k = 0; k < 4; ++k) acc[mi][ni][k] = 0.f;

        int pre = kcnt < NSTG ? kcnt : NSTG;
#pragma unroll
        for (int s = 0; s < NSTG; ++s) {
            if (s < pre)
                load_stage(sb + s * STAGEB, kt0 + s, tid, rowBase, colBase, Ah, Al, Bh, Bl);
            asm volatile("cp.async.commit_group;" ::: "memory");
        }

        for (int i = 0; i < kcnt; ++i) {
            if (pre == NSTG) {
                asm volatile("cp.async.wait_group 2;" ::: "memory");
            } else {
                asm volatile("cp.async.wait_group 0;" ::: "memory");
            }
            __syncthreads();
            uint32_t stg = sb + (uint32_t)(i % NSTG) * STAGEB;
#pragma unroll
            for (int ks = 0; ks < BKt; ks += 16) {
                uint32_t ah[4][4], al2[4][4], bh2[4][2], bl2[4][2];
#pragma unroll
                for (int mi = 0; mi < 4; ++mi) {
                    uint32_t a = stg + (aRow + mi * 16) * ROWB + (aK + ks) * 2;
                    ldsm4(ah[mi], a);
                    ldsm4(al2[mi], a + TILEB);
                }
#pragma unroll
                for (int ni = 0; ni < 4; ++ni) {
                    uint32_t a = stg + 2 * TILEB + (bRow + ni * 8) * ROWB + (bK + ks) * 2;
                    ldsm2(bh2[ni], a);
                    ldsm2(bl2[ni], a + TILEB);
                }
#pragma unroll
                for (int mi = 0; mi < 4; ++mi)
#pragma unroll
                    for (int ni = 0; ni < 4; ++ni) {
                        mma_bf16(acc[mi][ni], ah[mi], bh2[ni]);
                        mma_bf16(acc[mi][ni], ah[mi], bl2[ni]);
                        mma_bf16(acc[mi][ni], al2[mi], bh2[ni]);
                    }
            }
            __syncthreads();
            if (i + NSTG < kcnt)
                load_stage(stg, kt0 + i + NSTG, tid, rowBase, colBase, Ah, Al, Bh, Bl);
            asm volatile("cp.async.commit_group;" ::: "memory");
        }
        __syncthreads();   // smem stages now reusable as Cst

        // ---- pass 1: frags -> smem Cst [n][132] ----
        float* Cst = (float*)smem;
#pragma unroll
        for (int mi = 0; mi < 4; ++mi)
#pragma unroll
            for (int ni = 0; ni < 4; ++ni) {
                int m = mb + mi * 16 + (lane >> 2);
                int n = nb + ni * 8 + (lane & 3) * 2;
                Cst[n * 132 + m] = acc[mi][ni][0];
                Cst[(n + 1) * 132 + m] = acc[mi][ni][1];
                Cst[n * 132 + m + 8] = acc[mi][ni][2];
                Cst[(n + 1) * 132 + m + 8] = acc[mi][ni][3];
            }
        __syncthreads();

        // ---- store my partial to my slot (plain, coalesced) ----
        int firstOwner = (int)((((long long)(tile << 7) + 1) * nsm - 1) / TOTC);
        int lastOwner  = (int)((((long long)(tile << 7) + NCHUNK) * nsm - 1) / TOTC);
        int slot = cid - firstOwner;
        int nslots = lastOwner - firstOwner + 1;
        float* part = g_Cpart + ((size_t)(tile * 3 + slot) << 14);
#pragma unroll
        for (int it = 0; it < 16; ++it) {
            int lin = it * 1024 + tid * 4;
            int n = lin >> 7, m = lin & 127;
            *(float4*)&part[lin] = *(float4*)&Cst[n * 132 + m];
        }
        __threadfence();
        __syncthreads();
        if (tid == 0) {
            int old = atomicAdd(&g_cnt[tile], kcnt);
            sflag = (old + kcnt == NCHUNK) ? 1 : 0;
        }
        __syncthreads();

        if (sflag) {
            __threadfence();   // acquire: other slots' data visible
            // sum the other slots into Cst
            for (int s = 0; s < nslots; ++s) {
                if (s == slot) continue;
                const float* op = g_Cpart + ((size_t)(tile * 3 + s) << 14);
#pragma unroll
                for (int it = 0; it < 16; ++it) {
                    int lin = it * 1024 + tid * 4;
                    int n = lin >> 7, m = lin & 127;
                    float4 a = *(float4*)&Cst[n * 132 + m];
                    float4 b = *(const float4*)&op[lin];
                    a.x += b.x; a.y += b.y; a.z += b.z; a.w += b.w;
                    *(float4*)&Cst[n * 132 + m] = a;
                }
            }
            __syncthreads();

            // ---- pass 2 (n-major): v = C + DT*M*e; Bhi/Blo out, zh partial
            float CA0 = Cc[0] * Amat[0] + Cc[1] * Amat[2];
            float CA1 = Cc[0] * Amat[1] + Cc[1] * Amat[3];
            {
                int n = tid >> 1;
                int m0 = (tid & 1) * 64;
                float e = CA0 * g_x[p][colBase + n] + CA1 * g_x[p][BB + colBase + n];
                __nv_bfloat16* __restrict__ Bhn = g_Bhi[q2];
                __nv_bfloat16* __restrict__ Bln = g_Blo[q2];
                size_t obase = (size_t)(colBase + n) * NN + rowBase;
                float zp = 0.f;
#pragma unroll
                for (int q = 0; q < 16; ++q) {
                    int m = m0 + q * 4;
                    float4 c = *(float4*)&Cst[n * 132 + m];
                    float4 mv4 = *(const float4*)&Mv[rowBase + m];
                    float4 z4 = *(const float4*)&Z[rowBase + m];
                    float4 v;
                    v.x = c.x + DTc * mv4.x * e;
                    v.y = c.y + DTc * mv4.y * e;
                    v.z = c.z + DTc * mv4.z * e;
                    v.w = c.w + DTc * mv4.w * e;
                    *(float4*)&Cst[n * 132 + m] = v;
                    zp += z4.x * v.x + z4.y * v.y + z4.z * v.z + z4.w * v.w;
                    union { __nv_bfloat16 h[4]; uint2 u; } ph, pl;
                    const float* vp = &v.x;
#pragma unroll
                    for (int j = 0; j < 4; ++j) {
                        __nv_bfloat16 hi = __float2bfloat16(vp[j]);
                        ph.h[j] = hi;
                        pl.h[j] = __float2bfloat16(vp[j] - __bfloat162float(hi));
                    }
                    *(uint2*)&Bhn[obase + m] = ph.u;
                    *(uint2*)&Bln[obase + m] = pl.u;
                }
                zp += __shfl_xor_sync(0xFFFFFFFFu, zp, 1);
                if ((tid & 1) == 0)
                    atomicAdd(&g_zha[q2][colBase + n], zp);
            }
            __syncthreads();

            // ---- pass 3 (m-major): traj_{t+1} h-block ----
            {
                int m = tid >> 1;
                int n0 = (tid & 1) * 64;
                size_t tb = (size_t)(rowBase + m) * BB + colBase + n0;
#pragma unroll
                for (int q = 0; q < 16; ++q) {
                    float4 v;
                    v.x = Cst[(n0 + q * 4 + 0) * 132 + m];
                    v.y = Cst[(n0 + q * 4 + 1) * 132 + m];
                    v.z = Cst[(n0 + q * 4 + 2) * 132 + m];
                    v.w = Cst[(n0 + q * 4 + 3) * 132 + m];
                    *(float4*)&trajh_next[tb + q * 4] = v;
                }
            }
            if (tid == 0) atomicExch(&g_cnt[tile], 0);   // restore for next step
        }
        __syncthreads();   // Cst reuse safe before next segment
        c0 += kcnt;
    }
}

// --------------------------------------------------------------------------
extern "C" void kernel_launch(void* const* d_in, const int* in_sizes, int n_in,
                              void* d_out, int out_size) {
    const float* x0 = (const float*)d_in[0];
    const float* x1 = (const float*)d_in[1];
    const float* h0 = (const float*)d_in[2];
    const float* A  = (const float*)d_in[3];
    const float* Bm = (const float*)d_in[4];
    const float* C  = (const float*)d_in[5];
    const float* Mv = (const float*)d_in[6];
    const float* Z  = (const float*)d_in[7];
    const float* U  = (const float*)d_in[8];
    const float* V  = (const float*)d_in[9];
    const float* W  = (const float*)d_in[10];

    long long per_step_full = (long long)BB * (NN + 2 + 1);
    int steps = (int)((long long)out_size / per_step_full);
    if ((long long)steps * per_step_full != (long long)out_size)
        steps = (int)((long long)out_size / ((long long)BB * (NN + 2)));

    float* out  = (float*)d_out;
    float* traj = out;
    float* con  = out + (size_t)steps * (NN + 2) * BB;

    int nsm = 0;
    cudaDeviceGetAttribute(&nsm, cudaDevAttrMultiProcessorCount, 0);
    if (nsm < 8 || nsm > 512) nsm = 148;

    cudaFuncSetAttribute(gemm_streamk_kernel,
                         cudaFuncAttributeMaxDynamicSharedMemorySize, SMEM_BYTES);

    build_split_kernel<<<dim3(NN / 4 / 256, NN), 256>>>(W, U, V, Mv, Z, C, Bm);
    init_all_kernel<<<dim3(NN / 32, BB / 32), dim3(32, 8)>>>(h0, x0, x1, Z, traj + 2 * BB);

    for (int t = 0; t < steps; ++t) {
        int p = t & 1;
        int do_mma = (t < steps - 1);
        float* traj_t = traj + (size_t)t * (NN + 2) * BB;
        float* trajh_next = traj + (size_t)(t + 1) * (NN + 2) * BB + 2 * BB;
        if (!do_mma) trajh_next = traj_t + 2 * BB;   // unused, keep in-bounds
        gemm_streamk_kernel<<<nsm, 256, SMEM_BYTES>>>(
            p, do_mma, nsm, Mv, C, A, Bm, Z,
            trajh_next, traj_t, con + (size_t)t * BB);
    }
}